// round 2
// baseline (speedup 1.0000x reference)
#include <cuda_runtime.h>
#include <cuda_bf16.h>
#include <math.h>

// Problem constants
#define Bq 2
#define Sq 2048
#define Dq 768
#define Hq 12
#define Vq 50257
#define Fq 3072
#define HDq 64
#define Mq (Bq * Sq)   // 4096 rows

// ---------------- scratch (static device memory; no allocation at runtime) ---
__device__ float g_x   [Mq * Dq];        // emb + pos
__device__ float g_qkv [Mq * 3 * Dq];    // qkv
__device__ float g_attn[Mq * Dq];        // attention output
__device__ float g_mha [Mq * Dq];        // proj + residual
__device__ float g_h1  [Mq * Dq];        // LN1 out
__device__ float g_ff  [Mq * Fq];        // relu(h1 W1 + b1)
__device__ float g_res2[Mq * Dq];        // ff W2 + b2 + h1
__device__ float g_h2  [Mq * Dq];        // LN2 out
__device__ float g_weff[Dq * Dq];        // sum_h W_o[h*768+m, n]

// ---------------- embedding + positional encoding ----------------------------
__global__ void embed_pos_kernel(const int* __restrict__ inp,
                                 const float* __restrict__ emb,
                                 float* __restrict__ x) {
    int row = blockIdx.x;              // 0..4095 = b*S + s
    int s = row % Sq;
    int tok = inp[row];
    const float* e = emb + (size_t)tok * Dq;
    float* xr = x + (size_t)row * Dq;
    for (int d = threadIdx.x; d < Dq; d += blockDim.x) {
        float ex = 2.0f * (float)d / (float)Dq;
        float denom = powf(10000.0f, ex);
        float val = (float)s / denom;
        float pe = (d & 1) ? cosf(val) : sinf(val);
        xr[d] = e[d] + pe;
    }
}

// ---------------- W_eff = sum over heads of W_o blocks -----------------------
__global__ void weff_kernel(const float* __restrict__ W_o, float* __restrict__ W_eff) {
    int idx = blockIdx.x * blockDim.x + threadIdx.x;
    if (idx >= Dq * Dq) return;
    int m = idx / Dq, n = idx % Dq;
    float s = 0.f;
    #pragma unroll
    for (int h = 0; h < Hq; h++)
        s += W_o[((size_t)h * Dq + m) * Dq + n];
    W_eff[idx] = s;
}

// ---------------- generic tiled SGEMM: C = A[MxK] B[KxN] (+bias)(+res)(relu) -
// BM=BN=128, BK=8, 256 threads, 8x8 per thread.
__global__ void __launch_bounds__(256)
sgemm_kernel(const float* __restrict__ A, const float* __restrict__ B,
             const float* __restrict__ bias, const float* __restrict__ res,
             float* __restrict__ C, int M, int N, int K, int relu) {
    const int BM = 128, BN = 128, BK = 8;
    __shared__ float As[BK][BM];
    __shared__ float Bs[BK][BN + 4];

    int tid = threadIdx.x;
    int tx = tid & 15, ty = tid >> 4;
    int m0 = blockIdx.y * BM, n0 = blockIdx.x * BN;

    int aRow = tid >> 1, aCol = (tid & 1) * 4;   // 128 rows x 8 cols of A
    int bRow = tid >> 5, bCol = (tid & 31) * 4;  // 8 rows x 128 cols of B

    float acc[8][8];
    #pragma unroll
    for (int i = 0; i < 8; i++)
        #pragma unroll
        for (int j = 0; j < 8; j++) acc[i][j] = 0.f;

    bool fastB = ((N & 3) == 0) && (n0 + BN <= N);

    for (int k0 = 0; k0 < K; k0 += BK) {
        // load A tile (transposed into smem)
        float4 av = *(const float4*)(A + (size_t)(m0 + aRow) * K + k0 + aCol);
        As[aCol + 0][aRow] = av.x;
        As[aCol + 1][aRow] = av.y;
        As[aCol + 2][aRow] = av.z;
        As[aCol + 3][aRow] = av.w;
        // load B tile
        const float* Bp = B + (size_t)(k0 + bRow) * N + n0 + bCol;
        if (fastB) {
            float4 bv = *(const float4*)Bp;
            Bs[bRow][bCol + 0] = bv.x;
            Bs[bRow][bCol + 1] = bv.y;
            Bs[bRow][bCol + 2] = bv.z;
            Bs[bRow][bCol + 3] = bv.w;
        } else {
            #pragma unroll
            for (int i = 0; i < 4; i++) {
                int n = n0 + bCol + i;
                Bs[bRow][bCol + i] = (n < N) ? Bp[i] : 0.f;
            }
        }
        __syncthreads();

        #pragma unroll
        for (int kk = 0; kk < BK; kk++) {
            float a[8], b[8];
            #pragma unroll
            for (int i = 0; i < 8; i++) a[i] = As[kk][ty * 8 + i];
            #pragma unroll
            for (int j = 0; j < 8; j++) b[j] = Bs[kk][tx * 8 + j];
            #pragma unroll
            for (int i = 0; i < 8; i++)
                #pragma unroll
                for (int j = 0; j < 8; j++)
                    acc[i][j] = fmaf(a[i], b[j], acc[i][j]);
        }
        __syncthreads();
    }

    // epilogue
    #pragma unroll
    for (int i = 0; i < 8; i++) {
        int m = m0 + ty * 8 + i;
        #pragma unroll
        for (int j = 0; j < 8; j++) {
            int n = n0 + tx * 8 + j;
            if (n < N) {
                float v = acc[i][j];
                if (bias) v += bias[n];
                if (res)  v += res[(size_t)m * N + n];
                if (relu) v = fmaxf(v, 0.f);
                C[(size_t)m * N + n] = v;
            }
        }
    }
}

// ---------------- flash attention (causal, HD=64) -----------------------------
// grid: (S/64, B*H), block: 64 threads; each thread owns one query row.
__global__ void __launch_bounds__(64)
attn_kernel(const float* __restrict__ qkv, float* __restrict__ out) {
    int qt = blockIdx.x;
    int bh = blockIdx.y;
    int b = bh / Hq, h = bh % Hq;
    int tid = threadIdx.x;
    int qrow = qt * 64 + tid;

    const float* base = qkv + (size_t)b * Sq * 3 * Dq;

    float qreg[64];
    {
        const float* qp = base + (size_t)qrow * 3 * Dq + h * HDq;
        #pragma unroll
        for (int d4 = 0; d4 < 16; d4++) {
            float4 v = ((const float4*)qp)[d4];
            qreg[d4 * 4 + 0] = v.x; qreg[d4 * 4 + 1] = v.y;
            qreg[d4 * 4 + 2] = v.z; qreg[d4 * 4 + 3] = v.w;
        }
    }

    float acc[64];
    #pragma unroll
    for (int d = 0; d < 64; d++) acc[d] = 0.f;
    float m = -INFINITY, l = 0.f;

    __shared__ float Ks[64][65];
    __shared__ float Vs[64][65];

    for (int kt = 0; kt <= qt; kt++) {
        const float* kp = base + (size_t)(kt * 64 + tid) * 3 * Dq + Dq + h * HDq;
        const float* vp = kp + Dq;
        #pragma unroll
        for (int d4 = 0; d4 < 16; d4++) {
            float4 kv = ((const float4*)kp)[d4];
            Ks[tid][d4 * 4 + 0] = kv.x; Ks[tid][d4 * 4 + 1] = kv.y;
            Ks[tid][d4 * 4 + 2] = kv.z; Ks[tid][d4 * 4 + 3] = kv.w;
            float4 vv = ((const float4*)vp)[d4];
            Vs[tid][d4 * 4 + 0] = vv.x; Vs[tid][d4 * 4 + 1] = vv.y;
            Vs[tid][d4 * 4 + 2] = vv.z; Vs[tid][d4 * 4 + 3] = vv.w;
        }
        __syncthreads();

        int kbase = kt * 64;
        #pragma unroll 1
        for (int c = 0; c < 64; c += 16) {
            float s[16];
            #pragma unroll
            for (int j = 0; j < 16; j++) {
                float dot = 0.f;
                #pragma unroll
                for (int d = 0; d < 64; d++)
                    dot = fmaf(qreg[d], Ks[c + j][d], dot);
                int kpos = kbase + c + j;
                s[j] = (kpos <= qrow) ? dot * 0.125f : -1e30f;
            }
            float mt = m;
            #pragma unroll
            for (int j = 0; j < 16; j++) mt = fmaxf(mt, s[j]);
            if (mt > m) {
                float sc = expf(m - mt);
                l *= sc;
                #pragma unroll
                for (int d = 0; d < 64; d++) acc[d] *= sc;
                m = mt;
            }
            #pragma unroll
            for (int j = 0; j < 16; j++) {
                float p = expf(s[j] - m);
                l += p;
                #pragma unroll
                for (int d = 0; d < 64; d++)
                    acc[d] = fmaf(p, Vs[c + j][d], acc[d]);
            }
        }
        __syncthreads();
    }

    float inv_l = 1.0f / l;
    float* op = out + ((size_t)(b * Sq + qrow)) * Dq + h * HDq;
    #pragma unroll
    for (int d = 0; d < 64; d++) op[d] = acc[d] * inv_l;
}

// ---------------- layernorm (row = 768) ---------------------------------------
__global__ void __launch_bounds__(256)
layernorm_kernel(const float* __restrict__ in, const float* __restrict__ g,
                 const float* __restrict__ b, float* __restrict__ out) {
    int row = blockIdx.x;
    const float* x = in + (size_t)row * Dq;
    __shared__ float sx[Dq];
    __shared__ float red[256];
    int tid = threadIdx.x;

    float s = 0.f;
    for (int i = tid; i < Dq; i += 256) { float v = x[i]; sx[i] = v; s += v; }
    red[tid] = s; __syncthreads();
    for (int o = 128; o > 0; o >>= 1) { if (tid < o) red[tid] += red[tid + o]; __syncthreads(); }
    float mean = red[0] / (float)Dq;
    __syncthreads();

    float s2 = 0.f;
    for (int i = tid; i < Dq; i += 256) { float d = sx[i] - mean; s2 += d * d; }
    red[tid] = s2; __syncthreads();
    for (int o = 128; o > 0; o >>= 1) { if (tid < o) red[tid] += red[tid + o]; __syncthreads(); }
    float rstd = rsqrtf(red[0] / (float)Dq + 1e-5f);

    float* o = out + (size_t)row * Dq;
    for (int i = tid; i < Dq; i += 256)
        o[i] = (sx[i] - mean) * rstd * g[i] + b[i];
}

// ---------------- launch ------------------------------------------------------
extern "C" void kernel_launch(void* const* d_in, const int* in_sizes, int n_in,
                              void* d_out, int out_size) {
    (void)in_sizes; (void)n_in; (void)out_size;
    const int*   inputs = (const int*)  d_in[0];
    const float* emb    = (const float*)d_in[1];
    const float* W_qkv  = (const float*)d_in[2];
    const float* b_qkv  = (const float*)d_in[3];
    const float* W_o    = (const float*)d_in[4];
    const float* b_o    = (const float*)d_in[5];
    const float* ln1_g  = (const float*)d_in[6];
    const float* ln1_b  = (const float*)d_in[7];
    const float* W_ff1  = (const float*)d_in[8];
    const float* b_ff1  = (const float*)d_in[9];
    const float* W_ff2  = (const float*)d_in[10];
    const float* b_ff2  = (const float*)d_in[11];
    const float* ln2_g  = (const float*)d_in[12];
    const float* ln2_b  = (const float*)d_in[13];
    const float* W_out  = (const float*)d_in[14];
    const float* b_out  = (const float*)d_in[15];
    float* out = (float*)d_out;

    float *x, *qkv, *attn, *mha, *h1, *ff, *res2, *h2, *weff;
    cudaGetSymbolAddress((void**)&x,    g_x);
    cudaGetSymbolAddress((void**)&qkv,  g_qkv);
    cudaGetSymbolAddress((void**)&attn, g_attn);
    cudaGetSymbolAddress((void**)&mha,  g_mha);
    cudaGetSymbolAddress((void**)&h1,   g_h1);
    cudaGetSymbolAddress((void**)&ff,   g_ff);
    cudaGetSymbolAddress((void**)&res2, g_res2);
    cudaGetSymbolAddress((void**)&h2,   g_h2);
    cudaGetSymbolAddress((void**)&weff, g_weff);

    // 1) x = emb[inputs] + pos
    embed_pos_kernel<<<Mq, 256>>>(inputs, emb, x);

    // 2) W_eff = sum_h W_o blocks
    weff_kernel<<<(Dq * Dq + 255) / 256, 256>>>(W_o, weff);

    // 3) qkv = x @ W_qkv + b_qkv           [4096, 2304]
    sgemm_kernel<<<dim3(3 * Dq / 128, Mq / 128), 256>>>(
        x, W_qkv, b_qkv, nullptr, qkv, Mq, 3 * Dq, Dq, 0);

    // 4) flash attention -> attn           [4096, 768]
    attn_kernel<<<dim3(Sq / 64, Bq * Hq), 64>>>(qkv, attn);

    // 5) mha = attn @ W_eff + b_o + x
    sgemm_kernel<<<dim3(Dq / 128, Mq / 128), 256>>>(
        attn, weff, b_o, x, mha, Mq, Dq, Dq, 0);

    // 6) h1 = LN1(mha)
    layernorm_kernel<<<Mq, 256>>>(mha, ln1_g, ln1_b, h1);

    // 7) ff = relu(h1 @ W_ff1 + b_ff1)     [4096, 3072]
    sgemm_kernel<<<dim3(Fq / 128, Mq / 128), 256>>>(
        h1, W_ff1, b_ff1, nullptr, ff, Mq, Fq, Dq, 1);

    // 8) res2 = ff @ W_ff2 + b_ff2 + h1
    sgemm_kernel<<<dim3(Dq / 128, Mq / 128), 256>>>(
        ff, W_ff2, b_ff2, h1, res2, Mq, Dq, Fq, 0);

    // 9) h2 = LN2(res2)
    layernorm_kernel<<<Mq, 256>>>(res2, ln2_g, ln2_b, h2);

    // 10) logits = h2 @ W_out + b_out      [4096, 50257]
    sgemm_kernel<<<dim3((Vq + 127) / 128, Mq / 128), 256>>>(
        h2, W_out, b_out, nullptr, out, Mq, Vq, Dq, 0);
}

// round 4
// speedup vs baseline: 2.4514x; 2.4514x over previous
#include <cuda_runtime.h>
#include <cuda_bf16.h>
#include <math.h>
#include <stdint.h>

#define Bq 2
#define Sq 2048
#define Dq 768
#define Hq 12
#define Vq 50257
#define Fq 3072
#define HDq 64
#define Mq (Bq * Sq)
#define VPAD 50432

// ---------------- scratch ----------------
__device__ float g_x[Mq * Dq];
__device__ float g_qkv[Mq * 3 * Dq];
__device__ float g_attn[Mq * Dq];
__device__ float g_mha[Mq * Dq];
__device__ float g_h1[Mq * Dq];
__device__ float g_ff[Mq * Fq];
__device__ float g_res2[Mq * Dq];
__device__ float g_h2[Mq * Dq];
__device__ float g_weff[Dq * Dq];
__device__ __nv_bfloat16 g_A2[(size_t)Mq * 3 * Fq];
__device__ __nv_bfloat16 g_Bqkv[(size_t)(3 * Dq) * (3 * Dq)];
__device__ __nv_bfloat16 g_Bprj[(size_t)Dq * (3 * Dq)];
__device__ __nv_bfloat16 g_Bff1[(size_t)Fq * (3 * Dq)];
__device__ __nv_bfloat16 g_Bff2[(size_t)Dq * (3 * Fq)];
__device__ __nv_bfloat16 g_Bout[(size_t)VPAD * (3 * Dq)];

// ---------------- helpers ----------------
__device__ __forceinline__ uint32_t smem_u32(const void* p) {
    uint32_t a;
    asm("{ .reg .u64 t; cvta.to.shared.u64 t, %1; cvt.u32.u64 %0, t; }" : "=r"(a) : "l"(p));
    return a;
}
#define CP_ASYNC16(s, g) \
    asm volatile("cp.async.cg.shared.global [%0], [%1], 16;" :: "r"((uint32_t)(s)), "l"(g) : "memory")
#define CP_COMMIT() asm volatile("cp.async.commit_group;" ::: "memory")
#define CP_WAIT1()  asm volatile("cp.async.wait_group 1;" ::: "memory")
#define LDMATRIX_X4(d, addr) \
    asm volatile("ldmatrix.sync.aligned.m8n8.x4.shared.b16 {%0,%1,%2,%3}, [%4];" \
        : "=r"((d)[0]), "=r"((d)[1]), "=r"((d)[2]), "=r"((d)[3]) : "r"(addr))
#define MMA16816(c, a, b0, b1) \
    asm volatile("mma.sync.aligned.m16n8k16.row.col.f32.bf16.bf16.f32 " \
        "{%0,%1,%2,%3}, {%4,%5,%6,%7}, {%8,%9}, {%0,%1,%2,%3};" \
        : "+f"((c)[0]), "+f"((c)[1]), "+f"((c)[2]), "+f"((c)[3]) \
        : "r"((a)[0]), "r"((a)[1]), "r"((a)[2]), "r"((a)[3]), "r"(b0), "r"(b1))

// ---------------- split-bf16 conversions ----------------
__global__ void convert_A_kernel(const float* __restrict__ src, __nv_bfloat16* __restrict__ dst, int K) {
    size_t idx = (size_t)blockIdx.x * 256 + threadIdx.x;
    if (idx >= (size_t)Mq * K) return;
    int m = (int)(idx / K), k = (int)(idx % K);
    float v = src[idx];
    __nv_bfloat16 hi = __float2bfloat16(v);
    __nv_bfloat16 lo = __float2bfloat16(v - __bfloat162float(hi));
    size_t base = (size_t)m * 3 * K;
    dst[base + k] = hi;
    dst[base + K + k] = lo;
    dst[base + 2 * K + k] = hi;
}
__global__ void convert_BT_kernel(const float* __restrict__ src, __nv_bfloat16* __restrict__ dst,
                                  int K, int N, int Npad) {
    __shared__ float tile[32][33];
    int kb = blockIdx.y * 32, nb = blockIdx.x * 32;
    int tx = threadIdx.x, ty = threadIdx.y;
    for (int r = ty; r < 32; r += 8) {
        int k = kb + r, n = nb + tx;
        tile[r][tx] = (k < K && n < N) ? src[(size_t)k * N + n] : 0.f;
    }
    __syncthreads();
    size_t K3 = (size_t)3 * K;
    for (int r = ty; r < 32; r += 8) {
        int n = nb + r, k = kb + tx;
        if (n < Npad && k < K) {
            float v = tile[tx][r];
            __nv_bfloat16 hi = __float2bfloat16(v);
            __nv_bfloat16 lo = __float2bfloat16(v - __bfloat162float(hi));
            size_t base = (size_t)n * K3;
            dst[base + k] = hi;
            dst[base + K + k] = hi;
            dst[base + 2 * K + k] = lo;
        }
    }
}

// ---------------- mma.sync bf16 GEMM ----------------
// C[4096 x Nreal] = A2[4096 x Kp] * B2T[Npad x Kp]^T  (+bias)(+res)(relu)
// BM=BN=128, BK=32, 3-stage cp.async, 8 warps (4m x 2n), warp tile 32x64.
#define BK 32
#define STG 3
#define STAGE_BYTES 16384   // A 8KB + B 8KB

__global__ void __launch_bounds__(256)
mma_gemm_kernel(const __nv_bfloat16* __restrict__ A2, const __nv_bfloat16* __restrict__ B2T,
                const float* __restrict__ bias, const float* __restrict__ res,
                float* __restrict__ C, int Kp, int Nreal, int relu) {
    __shared__ __align__(1024) char smem_raw[STG * STAGE_BYTES];
    const uint32_t sb = smem_u32(smem_raw);
    const int tid = threadIdx.x;
    const int wid = tid >> 5, l = tid & 31;
    const int wm = wid & 3, wn = wid >> 2;
    const int m0 = blockIdx.x * 128, n0 = blockIdx.y * 128;
    const int NIT = Kp / BK;

    // global->smem load mapping: thread t loads 2 chunks of A row t>>1 and 2 of B
    const int ldr = tid >> 1;
    const int ldc0 = (tid & 1) * 2;                     // logical chunk 0 or 2
    const __nv_bfloat16* Asrc = A2 + (size_t)(m0 + ldr) * Kp + ldc0 * 8;
    const __nv_bfloat16* Bsrc = B2T + (size_t)(n0 + ldr) * Kp + ldc0 * 8;
    const uint32_t axr = (ldr >> 1) & 3;
    const uint32_t st_off0 = ldr * 64 + (((uint32_t)ldc0 ^ axr) << 4);
    const uint32_t st_off1 = ldr * 64 + ((((uint32_t)ldc0 + 1) ^ axr) << 4);

    float acc[2][8][4];
    #pragma unroll
    for (int i = 0; i < 2; i++)
        #pragma unroll
        for (int j = 0; j < 8; j++)
            #pragma unroll
            for (int q = 0; q < 4; q++) acc[i][j][q] = 0.f;

    // prologue: stages 0,1
    #pragma unroll
    for (int s = 0; s < 2; s++) {
        uint32_t d = sb + s * STAGE_BYTES;
        size_t ko = (size_t)s * BK;
        CP_ASYNC16(d + st_off0, (const void*)(Asrc + ko));
        CP_ASYNC16(d + st_off1, (const void*)(Asrc + ko + 8));
        CP_ASYNC16(d + 8192 + st_off0, (const void*)(Bsrc + ko));
        CP_ASYNC16(d + 8192 + st_off1, (const void*)(Bsrc + ko + 8));
        CP_COMMIT();
    }

    // precomputed ldmatrix lane rows
    const int ra_base = wm * 32 + (l & 15);             // + mt*16
    const int ca = l >> 4;                              // 0/1
    const int rb_base = wn * 64 + ((l >> 4) << 3) + (l & 7);  // + np*16
    const int cb = (l >> 3) & 1;

    for (int it = 0; it < NIT; it++) {
        CP_WAIT1();
        __syncthreads();
        // issue stage it+2
        if (it + 2 < NIT) {
            int st = (it + 2) % STG;
            uint32_t d = sb + st * STAGE_BYTES;
            size_t ko = (size_t)(it + 2) * BK;
            CP_ASYNC16(d + st_off0, (const void*)(Asrc + ko));
            CP_ASYNC16(d + st_off1, (const void*)(Asrc + ko + 8));
            CP_ASYNC16(d + 8192 + st_off0, (const void*)(Bsrc + ko));
            CP_ASYNC16(d + 8192 + st_off1, (const void*)(Bsrc + ko + 8));
        }
        CP_COMMIT();

        const uint32_t sbase = sb + (it % STG) * STAGE_BYTES;
        #pragma unroll
        for (int ks = 0; ks < 2; ks++) {
            uint32_t a[2][4], b[4][4];
            #pragma unroll
            for (int mt = 0; mt < 2; mt++) {
                int r = ra_base + mt * 16;
                uint32_t addr = sbase + r * 64 +
                    ((((uint32_t)(ks * 2 + ca)) ^ ((r >> 1) & 3)) << 4);
                LDMATRIX_X4(a[mt], addr);
            }
            #pragma unroll
            for (int np = 0; np < 4; np++) {
                int r = rb_base + np * 16;
                uint32_t addr = sbase + 8192 + r * 64 +
                    ((((uint32_t)(ks * 2 + cb)) ^ ((r >> 1) & 3)) << 4);
                LDMATRIX_X4(b[np], addr);
            }
            #pragma unroll
            for (int mt = 0; mt < 2; mt++)
                #pragma unroll
                for (int nt = 0; nt < 8; nt++) {
                    uint32_t b0 = (nt & 1) ? b[nt >> 1][2] : b[nt >> 1][0];
                    uint32_t b1 = (nt & 1) ? b[nt >> 1][3] : b[nt >> 1][1];
                    MMA16816(acc[mt][nt], a[mt], b0, b1);
                }
        }
    }

    // epilogue
    #pragma unroll
    for (int mt = 0; mt < 2; mt++) {
        int row = m0 + wm * 32 + mt * 16 + (l >> 2);
        #pragma unroll
        for (int nt = 0; nt < 8; nt++) {
            int col = n0 + wn * 64 + nt * 8 + (l & 3) * 2;
            #pragma unroll
            for (int half = 0; half < 2; half++) {
                int r = row + half * 8;
                #pragma unroll
                for (int e = 0; e < 2; e++) {
                    int cc = col + e;
                    if (cc < Nreal) {
                        float v = acc[mt][nt][half * 2 + e] + bias[cc];
                        if (relu) v = fmaxf(v, 0.f);
                        if (res) v += res[(size_t)r * Nreal + cc];
                        C[(size_t)r * Nreal + cc] = v;
                    }
                }
            }
        }
    }
}

// ---------------- embedding + positional ----------------
__global__ void embed_pos_kernel(const int* __restrict__ inp, const float* __restrict__ emb,
                                 float* __restrict__ x) {
    int row = blockIdx.x;
    int s = row % Sq;
    int tok = inp[row];
    const float* e = emb + (size_t)tok * Dq;
    float* xr = x + (size_t)row * Dq;
    for (int d = threadIdx.x; d < Dq; d += blockDim.x) {
        float denom = powf(10000.0f, 2.0f * (float)d / (float)Dq);
        float val = (float)s / denom;
        float pe = (d & 1) ? cosf(val) : sinf(val);
        xr[d] = e[d] + pe;
    }
}
__global__ void weff_kernel(const float* __restrict__ W_o, float* __restrict__ W_eff) {
    int idx = blockIdx.x * blockDim.x + threadIdx.x;
    if (idx >= Dq * Dq) return;
    int m = idx / Dq, n = idx % Dq;
    float s = 0.f;
    #pragma unroll
    for (int h = 0; h < Hq; h++) s += W_o[((size_t)h * Dq + m) * Dq + n];
    W_eff[idx] = s;
}

// ---------------- flash attention (causal, HD=64) ----------------
__global__ void __launch_bounds__(64)
attn_kernel(const float* __restrict__ qkv, float* __restrict__ out) {
    int qt = blockIdx.x, bh = blockIdx.y;
    int b = bh / Hq, h = bh % Hq;
    int tid = threadIdx.x;
    int qrow = qt * 64 + tid;
    const float* base = qkv + (size_t)b * Sq * 3 * Dq;

    float qreg[64];
    {
        const float* qp = base + (size_t)qrow * 3 * Dq + h * HDq;
        #pragma unroll
        for (int d4 = 0; d4 < 16; d4++) {
            float4 v = ((const float4*)qp)[d4];
            qreg[d4 * 4 + 0] = v.x; qreg[d4 * 4 + 1] = v.y;
            qreg[d4 * 4 + 2] = v.z; qreg[d4 * 4 + 3] = v.w;
        }
    }
    float acc[64];
    #pragma unroll
    for (int d = 0; d < 64; d++) acc[d] = 0.f;
    float m = -INFINITY, l = 0.f;
    __shared__ float Ks[64][65];
    __shared__ float Vs[64][65];

    for (int kt = 0; kt <= qt; kt++) {
        const float* kp = base + (size_t)(kt * 64 + tid) * 3 * Dq + Dq + h * HDq;
        const float* vp = kp + Dq;
        #pragma unroll
        for (int d4 = 0; d4 < 16; d4++) {
            float4 kv = ((const float4*)kp)[d4];
            Ks[tid][d4 * 4 + 0] = kv.x; Ks[tid][d4 * 4 + 1] = kv.y;
            Ks[tid][d4 * 4 + 2] = kv.z; Ks[tid][d4 * 4 + 3] = kv.w;
            float4 vv = ((const float4*)vp)[d4];
            Vs[tid][d4 * 4 + 0] = vv.x; Vs[tid][d4 * 4 + 1] = vv.y;
            Vs[tid][d4 * 4 + 2] = vv.z; Vs[tid][d4 * 4 + 3] = vv.w;
        }
        __syncthreads();
        int kbase = kt * 64;
        #pragma unroll 1
        for (int c = 0; c < 64; c += 16) {
            float s[16];
            #pragma unroll
            for (int j = 0; j < 16; j++) {
                float dot = 0.f;
                #pragma unroll
                for (int d = 0; d < 64; d++) dot = fmaf(qreg[d], Ks[c + j][d], dot);
                int kpos = kbase + c + j;
                s[j] = (kpos <= qrow) ? dot * 0.125f : -1e30f;
            }
            float mt = m;
            #pragma unroll
            for (int j = 0; j < 16; j++) mt = fmaxf(mt, s[j]);
            if (mt > m) {
                float sc = expf(m - mt);
                l *= sc;
                #pragma unroll
                for (int d = 0; d < 64; d++) acc[d] *= sc;
                m = mt;
            }
            #pragma unroll
            for (int j = 0; j < 16; j++) {
                float p = expf(s[j] - m);
                l += p;
                #pragma unroll
                for (int d = 0; d < 64; d++) acc[d] = fmaf(p, Vs[c + j][d], acc[d]);
            }
        }
        __syncthreads();
    }
    float inv_l = 1.0f / l;
    float* op = out + ((size_t)(b * Sq + qrow)) * Dq + h * HDq;
    #pragma unroll
    for (int d = 0; d < 64; d++) op[d] = acc[d] * inv_l;
}

// ---------------- layernorm ----------------
__global__ void __launch_bounds__(256)
layernorm_kernel(const float* __restrict__ in, const float* __restrict__ g,
                 const float* __restrict__ b, float* __restrict__ out) {
    int row = blockIdx.x;
    const float* x = in + (size_t)row * Dq;
    __shared__ float sx[Dq];
    __shared__ float red[256];
    int tid = threadIdx.x;
    float s = 0.f;
    for (int i = tid; i < Dq; i += 256) { float v = x[i]; sx[i] = v; s += v; }
    red[tid] = s; __syncthreads();
    for (int o = 128; o > 0; o >>= 1) { if (tid < o) red[tid] += red[tid + o]; __syncthreads(); }
    float mean = red[0] / (float)Dq;
    __syncthreads();
    float s2 = 0.f;
    for (int i = tid; i < Dq; i += 256) { float d = sx[i] - mean; s2 += d * d; }
    red[tid] = s2; __syncthreads();
    for (int o = 128; o > 0; o >>= 1) { if (tid < o) red[tid] += red[tid + o]; __syncthreads(); }
    float rstd = rsqrtf(red[0] / (float)Dq + 1e-5f);
    float* o = out + (size_t)row * Dq;
    for (int i = tid; i < Dq; i += 256)
        o[i] = (sx[i] - mean) * rstd * g[i] + b[i];
}

// ---------------- launch ----------------
static inline void conv_A(const float* src, __nv_bfloat16* dst, int K) {
    size_t n = (size_t)Mq * K;
    convert_A_kernel<<<(unsigned)((n + 255) / 256), 256>>>(src, dst, K);
}
static inline void conv_BT(const float* src, __nv_bfloat16* dst, int K, int N, int Npad) {
    convert_BT_kernel<<<dim3((Npad + 31) / 32, (K + 31) / 32), dim3(32, 8)>>>(src, dst, K, N, Npad);
}
static inline void run_gemm(const __nv_bfloat16* A2, const __nv_bfloat16* B2T,
                            const float* bias, const float* res, float* C,
                            int K, int Nreal, int Npad, int relu) {
    mma_gemm_kernel<<<dim3(Mq / 128, Npad / 128), 256>>>(A2, B2T, bias, res, C, 3 * K, Nreal, relu);
}

extern "C" void kernel_launch(void* const* d_in, const int* in_sizes, int n_in,
                              void* d_out, int out_size) {
    (void)in_sizes; (void)n_in; (void)out_size;
    const int*   inputs = (const int*)d_in[0];
    const float* emb   = (const float*)d_in[1];
    const float* W_qkv = (const float*)d_in[2];
    const float* b_qkv = (const float*)d_in[3];
    const float* W_o   = (const float*)d_in[4];
    const float* b_o   = (const float*)d_in[5];
    const float* ln1_g = (const float*)d_in[6];
    const float* ln1_b = (const float*)d_in[7];
    const float* W_ff1 = (const float*)d_in[8];
    const float* b_ff1 = (const float*)d_in[9];
    const float* W_ff2 = (const float*)d_in[10];
    const float* b_ff2 = (const float*)d_in[11];
    const float* ln2_g = (const float*)d_in[12];
    const float* ln2_b = (const float*)d_in[13];
    const float* W_out = (const float*)d_in[14];
    const float* b_out = (const float*)d_in[15];
    float* out = (float*)d_out;

    float *x, *qkv, *attn, *mha, *h1, *ff, *res2, *h2, *weff;
    cudaGetSymbolAddress((void**)&x, g_x);
    cudaGetSymbolAddress((void**)&qkv, g_qkv);
    cudaGetSymbolAddress((void**)&attn, g_attn);
    cudaGetSymbolAddress((void**)&mha, g_mha);
    cudaGetSymbolAddress((void**)&h1, g_h1);
    cudaGetSymbolAddress((void**)&ff, g_ff);
    cudaGetSymbolAddress((void**)&res2, g_res2);
    cudaGetSymbolAddress((void**)&h2, g_h2);
    cudaGetSymbolAddress((void**)&weff, g_weff);
    __nv_bfloat16 *A2, *Bqkv, *Bprj, *Bff1, *Bff2, *Bout;
    cudaGetSymbolAddress((void**)&A2, g_A2);
    cudaGetSymbolAddress((void**)&Bqkv, g_Bqkv);
    cudaGetSymbolAddress((void**)&Bprj, g_Bprj);
    cudaGetSymbolAddress((void**)&Bff1, g_Bff1);
    cudaGetSymbolAddress((void**)&Bff2, g_Bff2);
    cudaGetSymbolAddress((void**)&Bout, g_Bout);

    embed_pos_kernel<<<Mq, 256>>>(inputs, emb, x);
    weff_kernel<<<(Dq * Dq + 255) / 256, 256>>>(W_o, weff);

    // qkv = x @ W_qkv + b_qkv
    conv_A(x, A2, Dq);
    conv_BT(W_qkv, Bqkv, Dq, 3 * Dq, 3 * Dq);
    run_gemm(A2, Bqkv, b_qkv, nullptr, qkv, Dq, 3 * Dq, 3 * Dq, 0);

    // attention
    attn_kernel<<<dim3(Sq / 64, Bq * Hq), 64>>>(qkv, attn);

    // mha = attn @ W_eff + b_o + x
    conv_A(attn, A2, Dq);
    conv_BT(weff, Bprj, Dq, Dq, Dq);
    run_gemm(A2, Bprj, b_o, x, mha, Dq, Dq, Dq, 0);

    layernorm_kernel<<<Mq, 256>>>(mha, ln1_g, ln1_b, h1);

    // ff = relu(h1 @ W_ff1 + b_ff1)
    conv_A(h1, A2, Dq);
    conv_BT(W_ff1, Bff1, Dq, Fq, Fq);
    run_gemm(A2, Bff1, b_ff1, nullptr, ff, Dq, Fq, Fq, 1);

    // res2 = ff @ W_ff2 + b_ff2 + h1
    conv_A(ff, A2, Fq);
    conv_BT(W_ff2, Bff2, Fq, Dq, Dq);
    run_gemm(A2, Bff2, b_ff2, h1, res2, Fq, Dq, Dq, 0);

    layernorm_kernel<<<Mq, 256>>>(res2, ln2_g, ln2_b, h2);

    // logits = h2 @ W_out + b_out
    conv_A(h2, A2, Dq);
    conv_BT(W_out, Bout, Dq, Vq, VPAD);
    run_gemm(A2, Bout, b_out, nullptr, out, Dq, Vq, VPAD, 0);
}

// round 9
// speedup vs baseline: 3.2126x; 1.3105x over previous
#include <cuda_runtime.h>
#include <cuda_fp16.h>
#include <math.h>
#include <stdint.h>

#define Bq 2
#define Sq 2048
#define Dq 768
#define Hq 12
#define Vq 50257
#define Fq 3072
#define HDq 64
#define Mq (Bq * Sq)
#define VPAD 50432

// ---------------- scratch ----------------
__device__ float g_x[Mq * Dq];
__device__ float g_qkv[Mq * 3 * Dq];
__device__ float g_mha[Mq * Dq];
__device__ float g_h1[Mq * Dq];
__device__ float g_ff[Mq * Fq];
__device__ float g_res2[Mq * Dq];
__device__ float g_weff[Dq * Dq];
__device__ __half g_A2[(size_t)Mq * 3 * Fq];
__device__ __half g_Bqkv[(size_t)(3 * Dq) * (3 * Dq)];
__device__ __half g_Bprj[(size_t)Dq * (3 * Dq)];
__device__ __half g_Bff1[(size_t)Fq * (3 * Dq)];
__device__ __half g_Bff2[(size_t)Dq * (3 * Fq)];
__device__ __half g_Bout[(size_t)VPAD * (2 * Dq)];

// ---------------- helpers ----------------
__device__ __forceinline__ uint32_t smem_u32(const void* p) {
    uint32_t a;
    asm("{ .reg .u64 t; cvta.to.shared.u64 t, %1; cvt.u32.u64 %0, t; }" : "=r"(a) : "l"(p));
    return a;
}
#define CP_ASYNC16(s, g) \
    asm volatile("cp.async.cg.shared.global [%0], [%1], 16;" :: "r"((uint32_t)(s)), "l"(g) : "memory")
#define CP_COMMIT() asm volatile("cp.async.commit_group;" ::: "memory")
#define CP_WAIT1()  asm volatile("cp.async.wait_group 1;" ::: "memory")
#define LDMATRIX_X4(d, addr) \
    asm volatile("ldmatrix.sync.aligned.m8n8.x4.shared.b16 {%0,%1,%2,%3}, [%4];" \
        : "=r"((d)[0]), "=r"((d)[1]), "=r"((d)[2]), "=r"((d)[3]) : "r"(addr))
#define MMA16816(c, a, b0, b1) \
    asm volatile("mma.sync.aligned.m16n8k16.row.col.f32.f16.f16.f32 " \
        "{%0,%1,%2,%3}, {%4,%5,%6,%7}, {%8,%9}, {%0,%1,%2,%3};" \
        : "+f"((c)[0]), "+f"((c)[1]), "+f"((c)[2]), "+f"((c)[3]) \
        : "r"((a)[0]), "r"((a)[1]), "r"((a)[2]), "r"((a)[3]), "r"(b0), "r"(b1))

__device__ __forceinline__ void split_store(__half* p, float v, size_t o, int K, int nterms) {
    __half hi = __float2half_rn(v);
    __half lo = __float2half_rn(v - __half2float(hi));
    p[o] = hi;
    p[o + K] = lo;
    if (nterms == 3) p[o + 2 * (size_t)K] = hi;
}

// ---------------- conversions ----------------
__global__ void convert_A_kernel(const float* __restrict__ src, __half* __restrict__ dst,
                                 int K, int nterms) {
    size_t idx = (size_t)blockIdx.x * 256 + threadIdx.x;
    if (idx >= (size_t)Mq * K) return;
    int m = (int)(idx / K), k = (int)(idx % K);
    split_store(dst, src[idx], (size_t)m * nterms * K + k, K, nterms);
}
// B: [hi | hi (| lo)]
__global__ void convert_BT_kernel(const float* __restrict__ src, __half* __restrict__ dst,
                                  int K, int N, int Npad, int nterms) {
    __shared__ float tile[32][33];
    int kb = blockIdx.y * 32, nb = blockIdx.x * 32;
    int tx = threadIdx.x, ty = threadIdx.y;
    for (int r = ty; r < 32; r += 8) {
        int k = kb + r, n = nb + tx;
        tile[r][tx] = (k < K && n < N) ? src[(size_t)k * N + n] : 0.f;
    }
    __syncthreads();
    size_t Ks = (size_t)nterms * K;
    for (int r = ty; r < 32; r += 8) {
        int n = nb + r, k = kb + tx;
        if (n < Npad && k < K) {
            float v = tile[tx][r];
            __half hi = __float2half_rn(v);
            __half lo = __float2half_rn(v - __half2float(hi));
            size_t base = (size_t)n * Ks;
            dst[base + k] = hi;
            dst[base + K + k] = hi;
            if (nterms == 3) dst[base + 2 * K + k] = lo;
        }
    }
}

// ---------------- mma.sync fp16 GEMM ----------------
#define BK 32
#define STG 3
#define STAGE_BYTES 16384

__global__ void __launch_bounds__(256)
mma_gemm_kernel(const __half* __restrict__ A2, const __half* __restrict__ B2T,
                const float* __restrict__ bias, const float* __restrict__ res,
                float* __restrict__ C, int Kp, int Nreal, int relu) {
    __shared__ __align__(1024) char smem_raw[STG * STAGE_BYTES];
    const uint32_t sb = smem_u32(smem_raw);
    const int tid = threadIdx.x;
    const int wid = tid >> 5, l = tid & 31;
    const int wm = wid & 3, wn = wid >> 2;
    const int m0 = blockIdx.x * 128, n0 = blockIdx.y * 128;
    const int NIT = Kp / BK;

    const int ldr = tid >> 1;
    const int ldc0 = (tid & 1) * 2;
    const __half* Asrc = A2 + (size_t)(m0 + ldr) * Kp + ldc0 * 8;
    const __half* Bsrc = B2T + (size_t)(n0 + ldr) * Kp + ldc0 * 8;
    const uint32_t axr = (ldr >> 1) & 3;
    const uint32_t st_off0 = ldr * 64 + (((uint32_t)ldc0 ^ axr) << 4);
    const uint32_t st_off1 = ldr * 64 + ((((uint32_t)ldc0 + 1) ^ axr) << 4);

    float acc[2][8][4];
    #pragma unroll
    for (int i = 0; i < 2; i++)
        #pragma unroll
        for (int j = 0; j < 8; j++)
            #pragma unroll
            for (int q = 0; q < 4; q++) acc[i][j][q] = 0.f;

    #pragma unroll
    for (int s = 0; s < 2; s++) {
        uint32_t d = sb + s * STAGE_BYTES;
        size_t ko = (size_t)s * BK;
        CP_ASYNC16(d + st_off0, (const void*)(Asrc + ko));
        CP_ASYNC16(d + st_off1, (const void*)(Asrc + ko + 8));
        CP_ASYNC16(d + 8192 + st_off0, (const void*)(Bsrc + ko));
        CP_ASYNC16(d + 8192 + st_off1, (const void*)(Bsrc + ko + 8));
        CP_COMMIT();
    }

    const int ra_base = wm * 32 + (l & 15);
    const int ca = l >> 4;
    const int rb_base = wn * 64 + ((l >> 4) << 3) + (l & 7);
    const int cb = (l >> 3) & 1;

    for (int it = 0; it < NIT; it++) {
        CP_WAIT1();
        __syncthreads();
        if (it + 2 < NIT) {
            int st = (it + 2) % STG;
            uint32_t d = sb + st * STAGE_BYTES;
            size_t ko = (size_t)(it + 2) * BK;
            CP_ASYNC16(d + st_off0, (const void*)(Asrc + ko));
            CP_ASYNC16(d + st_off1, (const void*)(Asrc + ko + 8));
            CP_ASYNC16(d + 8192 + st_off0, (const void*)(Bsrc + ko));
            CP_ASYNC16(d + 8192 + st_off1, (const void*)(Bsrc + ko + 8));
        }
        CP_COMMIT();

        const uint32_t sbase = sb + (it % STG) * STAGE_BYTES;
        #pragma unroll
        for (int ks = 0; ks < 2; ks++) {
            uint32_t a[2][4], b[4][4];
            #pragma unroll
            for (int mt = 0; mt < 2; mt++) {
                int r = ra_base + mt * 16;
                uint32_t addr = sbase + r * 64 +
                    ((((uint32_t)(ks * 2 + ca)) ^ ((r >> 1) & 3)) << 4);
                LDMATRIX_X4(a[mt], addr);
            }
            #pragma unroll
            for (int np = 0; np < 4; np++) {
                int r = rb_base + np * 16;
                uint32_t addr = sbase + 8192 + r * 64 +
                    ((((uint32_t)(ks * 2 + cb)) ^ ((r >> 1) & 3)) << 4);
                LDMATRIX_X4(b[np], addr);
            }
            #pragma unroll
            for (int mt = 0; mt < 2; mt++)
                #pragma unroll
                for (int nt = 0; nt < 8; nt++) {
                    uint32_t b0 = (nt & 1) ? b[nt >> 1][2] : b[nt >> 1][0];
                    uint32_t b1 = (nt & 1) ? b[nt >> 1][3] : b[nt >> 1][1];
                    MMA16816(acc[mt][nt], a[mt], b0, b1);
                }
        }
    }

    #pragma unroll
    for (int mt = 0; mt < 2; mt++) {
        int row = m0 + wm * 32 + mt * 16 + (l >> 2);
        #pragma unroll
        for (int nt = 0; nt < 8; nt++) {
            int col = n0 + wn * 64 + nt * 8 + (l & 3) * 2;
            #pragma unroll
            for (int half = 0; half < 2; half++) {
                int r = row + half * 8;
                #pragma unroll
                for (int e = 0; e < 2; e++) {
                    int cc = col + e;
                    if (cc < Nreal) {
                        float v = acc[mt][nt][half * 2 + e] + bias[cc];
                        if (relu) v = fmaxf(v, 0.f);
                        if (res) v += res[(size_t)r * Nreal + cc];
                        C[(size_t)r * Nreal + cc] = v;
                    }
                }
            }
        }
    }
}

// ---------------- embedding + positional, fused split write ----------------
__global__ void embed_pos_kernel(const int* __restrict__ inp, const float* __restrict__ emb,
                                 float* __restrict__ x, __half* __restrict__ a2) {
    int row = blockIdx.x;
    int s = row % Sq;
    int tok = inp[row];
    const float* e = emb + (size_t)tok * Dq;
    for (int d = threadIdx.x; d < Dq; d += blockDim.x) {
        float denom = powf(10000.0f, 2.0f * (float)d / (float)Dq);
        float val = (float)s / denom;
        float pe = (d & 1) ? cosf(val) : sinf(val);
        float v = e[d] + pe;
        x[(size_t)row * Dq + d] = v;
        split_store(a2, v, (size_t)row * 3 * Dq + d, Dq, 3);
    }
}
__global__ void weff_kernel(const float* __restrict__ W_o, float* __restrict__ W_eff) {
    int idx = blockIdx.x * blockDim.x + threadIdx.x;
    if (idx >= Dq * Dq) return;
    int m = idx / Dq, n = idx % Dq;
    float s = 0.f;
    #pragma unroll
    for (int h = 0; h < Hq; h++) s += W_o[((size_t)h * Dq + m) * Dq + n];
    W_eff[idx] = s;
}

// ---------------- flash attention (fp32, paired-thread, fused split write) ----
__global__ void __launch_bounds__(256, 2)
attn_kernel(const float* __restrict__ qkv, __half* __restrict__ A2) {
    extern __shared__ float kvsm[];
    float* Ks = kvsm;
    float* Vs = kvsm + 64 * 68;
    int qt = blockIdx.x, bh = blockIdx.y;
    int b = bh / Hq, h = bh % Hq;
    int tid = threadIdx.x;
    int w = tid >> 5, l = tid & 31;
    int half = l >> 4;
    int qrow = qt * 128 + w * 16 + (l & 15);
    int qmaxw = qt * 128 + w * 16 + 15;
    const float* base = qkv + (size_t)b * Sq * 2304;

    int ro[8];
    #pragma unroll
    for (int q = 0; q < 8; q++) ro[q] = half ? ((q + 1) & 7) : q;

    float4 qv[8];
    {
        const float4* qp4 = (const float4*)(base + (size_t)qrow * 2304 + h * 64 + half * 32);
        #pragma unroll
        for (int q = 0; q < 8; q++) qv[q] = qp4[ro[q]];
    }
    float4 acc[8];
    #pragma unroll
    for (int q = 0; q < 8; q++) acc[q] = make_float4(0.f, 0.f, 0.f, 0.f);
    float mx = -INFINITY, lsum = 0.f;

    int lr = tid >> 2, lq = (tid & 3) * 4;
    const float* kg = base + 768 + h * 64;
    const float* vg = base + 1536 + h * 64;

    int ktmax = 2 * qt + 1;
    for (int kt = 0; kt <= ktmax; kt++) {
        const float4* kp4 = (const float4*)(kg + (size_t)(kt * 64 + lr) * 2304) + lq;
        const float4* vp4 = (const float4*)(vg + (size_t)(kt * 64 + lr) * 2304) + lq;
        float4* ks4 = (float4*)(Ks + lr * 68) + lq;
        float4* vs4 = (float4*)(Vs + lr * 68) + lq;
        #pragma unroll
        for (int q = 0; q < 4; q++) { ks4[q] = kp4[q]; vs4[q] = vp4[q]; }
        __syncthreads();
        int kb = kt * 64;
        if (kb <= qmaxw) {
            #pragma unroll 1
            for (int c = 0; c < 64; c += 16) {
                if (kb + c > qmaxw) break;
                float s[16];
                #pragma unroll
                for (int j = 0; j < 16; j++) {
                    const float4* kk = (const float4*)(Ks + (c + j) * 68 + half * 32);
                    float dot = 0.f;
                    #pragma unroll
                    for (int q = 0; q < 8; q++) {
                        float4 kq = kk[ro[q]];
                        dot = fmaf(qv[q].x, kq.x, dot);
                        dot = fmaf(qv[q].y, kq.y, dot);
                        dot = fmaf(qv[q].z, kq.z, dot);
                        dot = fmaf(qv[q].w, kq.w, dot);
                    }
                    dot += __shfl_xor_sync(0xffffffffu, dot, 16);
                    s[j] = (kb + c + j <= qrow) ? dot * 0.125f : -1e30f;
                }
                float mt = mx;
                #pragma unroll
                for (int j = 0; j < 16; j++) mt = fmaxf(mt, s[j]);
                if (mt > mx) {
                    float sc = __expf(mx - mt);
                    lsum *= sc;
                    #pragma unroll
                    for (int q = 0; q < 8; q++) {
                        acc[q].x *= sc; acc[q].y *= sc; acc[q].z *= sc; acc[q].w *= sc;
                    }
                    mx = mt;
                }
                #pragma unroll
                for (int j = 0; j < 16; j++) {
                    float p = __expf(s[j] - mx);
                    lsum += p;
                    const float4* vv = (const float4*)(Vs + (c + j) * 68 + half * 32);
                    #pragma unroll
                    for (int q = 0; q < 8; q++) {
                        float4 vq = vv[ro[q]];
                        acc[q].x = fmaf(p, vq.x, acc[q].x);
                        acc[q].y = fmaf(p, vq.y, acc[q].y);
                        acc[q].z = fmaf(p, vq.z, acc[q].z);
                        acc[q].w = fmaf(p, vq.w, acc[q].w);
                    }
                }
            }
        }
        __syncthreads();
    }
    float inv = 1.f / lsum;
    size_t obase = (size_t)(b * Sq + qrow) * 2304 + h * 64;   // FIXED: batch offset
    #pragma unroll
    for (int q = 0; q < 8; q++) {
        float vals[4] = {acc[q].x * inv, acc[q].y * inv, acc[q].z * inv, acc[q].w * inv};
        int d0 = half * 32 + ro[q] * 4;
        #pragma unroll
        for (int e = 0; e < 4; e++) {
            float v = vals[e];
            __half hi = __float2half_rn(v);
            __half lo = __float2half_rn(v - __half2float(hi));
            A2[obase + d0 + e] = hi;
            A2[obase + 768 + d0 + e] = lo;
            A2[obase + 1536 + d0 + e] = hi;
        }
    }
}

// ---------------- layernorm + fused split write ----------------
__global__ void __launch_bounds__(256)
layernorm_kernel(const float* __restrict__ in, const float* __restrict__ g,
                 const float* __restrict__ b, float* __restrict__ out,
                 __half* __restrict__ a2, int nterms) {
    int row = blockIdx.x;
    const float* x = in + (size_t)row * Dq;
    __shared__ float sx[Dq];
    __shared__ float red[256];
    int tid = threadIdx.x;
    float s = 0.f;
    for (int i = tid; i < Dq; i += 256) { float v = x[i]; sx[i] = v; s += v; }
    red[tid] = s; __syncthreads();
    for (int o = 128; o > 0; o >>= 1) { if (tid < o) red[tid] += red[tid + o]; __syncthreads(); }
    float mean = red[0] / (float)Dq;
    __syncthreads();
    float s2 = 0.f;
    for (int i = tid; i < Dq; i += 256) { float d = sx[i] - mean; s2 += d * d; }
    red[tid] = s2; __syncthreads();
    for (int o = 128; o > 0; o >>= 1) { if (tid < o) red[tid] += red[tid + o]; __syncthreads(); }
    float rstd = rsqrtf(red[0] / (float)Dq + 1e-5f);
    size_t abase = (size_t)row * nterms * Dq;
    for (int i = tid; i < Dq; i += 256) {
        float v = (sx[i] - mean) * rstd * g[i] + b[i];
        if (out) out[(size_t)row * Dq + i] = v;
        split_store(a2, v, abase + i, Dq, nterms);
    }
}

// ---------------- launch ----------------
static inline void conv_BT(const float* src, __half* dst, int K, int N, int Npad, int nterms) {
    convert_BT_kernel<<<dim3((Npad + 31) / 32, (K + 31) / 32), dim3(32, 8)>>>(src, dst, K, N, Npad, nterms);
}
static inline void run_gemm(const __half* A2, const __half* B2T,
                            const float* bias, const float* res, float* C,
                            int Kp, int Nreal, int Npad, int relu) {
    mma_gemm_kernel<<<dim3(Mq / 128, Npad / 128), 256>>>(A2, B2T, bias, res, C, Kp, Nreal, relu);
}

extern "C" void kernel_launch(void* const* d_in, const int* in_sizes, int n_in,
                              void* d_out, int out_size) {
    (void)in_sizes; (void)n_in; (void)out_size;
    const int*   inputs = (const int*)d_in[0];
    const float* emb   = (const float*)d_in[1];
    const float* W_qkv = (const float*)d_in[2];
    const float* b_qkv = (const float*)d_in[3];
    const float* W_o   = (const float*)d_in[4];
    const float* b_o   = (const float*)d_in[5];
    const float* ln1_g = (const float*)d_in[6];
    const float* ln1_b = (const float*)d_in[7];
    const float* W_ff1 = (const float*)d_in[8];
    const float* b_ff1 = (const float*)d_in[9];
    const float* W_ff2 = (const float*)d_in[10];
    const float* b_ff2 = (const float*)d_in[11];
    const float* ln2_g = (const float*)d_in[12];
    const float* ln2_b = (const float*)d_in[13];
    const float* W_out = (const float*)d_in[14];
    const float* b_out = (const float*)d_in[15];
    float* out = (float*)d_out;

    float *x, *qkv, *mha, *h1, *ff, *res2, *weff;
    cudaGetSymbolAddress((void**)&x, g_x);
    cudaGetSymbolAddress((void**)&qkv, g_qkv);
    cudaGetSymbolAddress((void**)&mha, g_mha);
    cudaGetSymbolAddress((void**)&h1, g_h1);
    cudaGetSymbolAddress((void**)&ff, g_ff);
    cudaGetSymbolAddress((void**)&res2, g_res2);
    cudaGetSymbolAddress((void**)&weff, g_weff);
    __half *A2, *Bqkv, *Bprj, *Bff1, *Bff2, *Bout;
    cudaGetSymbolAddress((void**)&A2, g_A2);
    cudaGetSymbolAddress((void**)&Bqkv, g_Bqkv);
    cudaGetSymbolAddress((void**)&Bprj, g_Bprj);
    cudaGetSymbolAddress((void**)&Bff1, g_Bff1);
    cudaGetSymbolAddress((void**)&Bff2, g_Bff2);
    cudaGetSymbolAddress((void**)&Bout, g_Bout);

    cudaFuncSetAttribute(attn_kernel, cudaFuncAttributeMaxDynamicSharedMemorySize, 2 * 64 * 68 * 4);

    // x = emb + pos (fp32 + split)
    embed_pos_kernel<<<Mq, 256>>>(inputs, emb, x, A2);
    weff_kernel<<<(Dq * Dq + 255) / 256, 256>>>(W_o, weff);

    // qkv = x @ W_qkv + b_qkv      (3-term, Kp=2304)
    conv_BT(W_qkv, Bqkv, Dq, 3 * Dq, 3 * Dq, 3);
    run_gemm(A2, Bqkv, b_qkv, nullptr, qkv, 3 * Dq, 3 * Dq, 3 * Dq, 0);

    // attention -> split A2 directly
    attn_kernel<<<dim3(Sq / 128, Bq * Hq), 256, 2 * 64 * 68 * 4>>>(qkv, A2);

    // mha = attn @ W_eff + b_o + x
    conv_BT(weff, Bprj, Dq, Dq, Dq, 3);
    run_gemm(A2, Bprj, b_o, x, mha, 3 * Dq, Dq, Dq, 0);

    // h1 = LN1(mha) (fp32 + split)
    layernorm_kernel<<<Mq, 256>>>(mha, ln1_g, ln1_b, h1, A2, 3);

    // ff = relu(h1 @ W_ff1 + b_ff1)
    conv_BT(W_ff1, Bff1, Dq, Fq, Fq, 3);
    run_gemm(A2, Bff1, b_ff1, nullptr, ff, 3 * Dq, Fq, Fq, 1);

    // split ff, res2 = ff @ W_ff2 + b_ff2 + h1   (Kp=9216)
    {
        size_t n = (size_t)Mq * Fq;
        convert_A_kernel<<<(unsigned)((n + 255) / 256), 256>>>(ff, A2, Fq, 3);
    }
    conv_BT(W_ff2, Bff2, Fq, Dq, Dq, 3);
    run_gemm(A2, Bff2, b_ff2, h1, res2, 3 * Fq, Dq, Dq, 0);

    // h2 = LN2(res2): split-only, 2-term (Kp=1536)
    layernorm_kernel<<<Mq, 256>>>(res2, ln2_g, ln2_b, nullptr, A2, 2);

    // logits = h2 @ W_out + b_out  (2-term)
    conv_BT(W_out, Bout, Dq, Vq, VPAD, 2);
    run_gemm(A2, Bout, b_out, nullptr, out, 2 * Dq, Vq, VPAD, 0);
}